// round 14
// baseline (speedup 1.0000x reference)
#include <cuda_runtime.h>
#include <cstdint>

typedef unsigned long long ull;

#define SEQ 64
#define DM 32
#define DI 64
#define HW 1024
#define TT 8

#define FMA2(d, a, b, c) \
    asm("fma.rn.f32x2 %0, %1, %2, %3;" : "=l"(d) : "l"(a), "l"(b), "l"(c))
#define MUL2(d, a, b) \
    asm("mul.rn.f32x2 %0, %1, %2;" : "=l"(d) : "l"(a), "l"(b))
__device__ __forceinline__ ull pack2(float lo, float hi) {
    ull r; asm("mov.b64 %0, {%1, %2};" : "=l"(r) : "f"(lo), "f"(hi)); return r;
}
__device__ __forceinline__ float2 unpack2(ull v) {
    float2 f; asm("mov.b64 {%0, %1}, %2;" : "=f"(f.x), "=f"(f.y) : "l"(v)); return f;
}
__device__ __forceinline__ float4 lds128(uint32_t a) {
    float4 v;
    asm volatile("ld.shared.v4.f32 {%0,%1,%2,%3}, [%4];"
                 : "=f"(v.x), "=f"(v.y), "=f"(v.z), "=f"(v.w) : "r"(a));
    return v;
}

__device__ float g_xr[2 * HW * SEQ * DM];

__global__ __launch_bounds__(256) void transpose_kernel(const float* __restrict__ x) {
    __shared__ float tile[DM][65];
    const int bi = blockIdx.x;
    const int c  = bi & 15;
    const int t  = (bi >> 4) & 63;
    const int b  = bi >> 10;
    const float* src = x + ((b * SEQ + t) * DM) * HW + c * 64;
    const int tid = threadIdx.x;
    #pragma unroll
    for (int i = 0; i < 8; i++) {
        int idx = tid + i * 256;
        tile[idx >> 6][idx & 63] = src[(idx >> 6) * HW + (idx & 63)];
    }
    __syncthreads();
    #pragma unroll
    for (int i = 0; i < 8; i++) {
        int idx = tid + i * 256;
        int hw = idx >> 5, m = idx & 31;
        g_xr[(b * HW + c * 64 + hw) * (SEQ * DM) + t * DM + m] = tile[m][hw];
    }
}

// 256 threads = 2 seqs x 128; thread = (seq j, channel d, half p). 3 CTAs/SM.
__global__ __launch_bounds__(256, 3) void mamba_main(
    const float* __restrict__ in_proj_w, const float* __restrict__ conv_w,
    const float* __restrict__ conv_b, const float* __restrict__ x_proj_w,
    const float* __restrict__ dt_proj_w, const float* __restrict__ dt_proj_b,
    const float* __restrict__ A_log, const float* __restrict__ Dp,
    const float* __restrict__ out_proj_w, const float* __restrict__ lin1_w,
    const float* __restrict__ lin1_b, const float* __restrict__ lin2_w,
    const float* __restrict__ lin2_b, float* __restrict__ out)
{
    __shared__ float4 winp4[8][128];        // [qq][r]: in_proj_w[r][4qq..]; r<64 xh, r>=64 z
    __shared__ float4 xpw4[4][128];         // [qq][i]: quarter-row weights, i=task id
    __shared__ float  wdt_s[2][64];         // dt rows 0/1
    __shared__ float  xin_s[2][2][TT][DM];  // double-buffered input tiles
    __shared__ float  xt_s[2][TT][64];      // natural layout
    __shared__ float  sz_s[2][TT][64];
    __shared__ float  dbc_s[2][TT][40];     // [0:16)B [16:32)C
    __shared__ float  dtp_s[2][TT][2][4];   // dt partials [row][warp]
    __shared__ float  part_s[2][SEQ][4];
    __shared__ float  wm_s[DM];
    __shared__ float  v_s[DI];
    __shared__ float  a_s[DI][18];
    __shared__ float  c_s;
    __shared__ int    slow_s;

    const int tid = threadIdx.x;
    const int j = tid >> 7;                 // seq in block
    const int u = tid & 127;
    const int w4 = u >> 5;                  // warp within seq (0..3)
    const int lane = tid & 31;
    const int d = 16 * w4 + (lane >> 1);    // channel
    const int p = lane & 1;                 // half index

    if (tid == 0) slow_s = 0;
    for (int idx = tid; idx < 1024; idx += 256) {
        int qq = idx >> 7, r = idx & 127;
        winp4[qq][r] = *(const float4*)&in_proj_w[r * DM + 4 * qq];
    }
    for (int idx = tid; idx < 512; idx += 256) {
        int qq = idx >> 7, i = idx & 127;
        int row = 2 + (i >> 2), half = (i >> 1) & 1, q = i & 1;
        xpw4[qq][i] = *(const float4*)&x_proj_w[row * DI + 32 * half + 16 * q + 4 * qq];
    }
    if (tid < 128) wdt_s[tid >> 6][tid & 63] = x_proj_w[(tid >> 6) * DI + (tid & 63)];
    if (tid < DM) {
        float acc = 0.f;
        #pragma unroll
        for (int k = 0; k < 16; k++) acc = fmaf(lin2_w[k], lin1_w[k * 32 + tid], acc);
        wm_s[tid] = acc;
    }
    if (tid == 0) {
        float c = lin2_b[0];
        #pragma unroll
        for (int k = 0; k < 16; k++) c = fmaf(lin2_w[k], lin1_b[k], c);
        c_s = c;
    }
    __syncthreads();
    if (tid < DI) {
        float acc = 0.f;
        #pragma unroll
        for (int m = 0; m < 32; m++) acc = fmaf(wm_s[m], out_proj_w[m * 64 + tid], acc);
        v_s[tid] = acc;
        int bad = 0;
        #pragma unroll
        for (int n = 0; n < 16; n++) {
            float a = -__expf(A_log[tid * 16 + n]);
            a_s[tid][n] = a;
            if (fabsf(a + (float)(n + 1)) > 1e-4f * (float)(n + 1)) bad = 1;
        }
        if (bad) atomicOr(&slow_s, 1);
    }

    const float4 cw = *(const float4*)(conv_w + d * 4);
    const float cb = conv_b[d];
    const float2 dtw = *(const float2*)(dt_proj_w + d * 2);
    const float dtb = dt_proj_b[d];
    const float dpv = Dp[d];

    const int bb0 = blockIdx.x * 2;
    // preload tile 0: 2 seqs x 64 float4
    if (tid < 128) {
        int s = tid >> 6, rem = tid & 63;
        float4 v4 = *(const float4*)(g_xr + (size_t)(bb0 + s) * (SEQ * DM) + rem * 4);
        *(float4*)&xin_s[0][s][rem >> 3][(rem & 7) * 4] = v4;
    }
    __syncthreads();
    const float vv = v_s[d];
    const int slow = slow_s;

    const uint32_t xt_a = (uint32_t)__cvta_generic_to_shared(&xt_s[j][0][0]);
    const uint32_t db_a = (uint32_t)__cvta_generic_to_shared(&dbc_s[j][0][0]);
    const uint32_t dtp_a = (uint32_t)__cvta_generic_to_shared(&dtp_s[j][0][0][0]);

    ull h2[4];                              // 8 states: [8p, 8p+8)
    #pragma unroll
    for (int q = 0; q < 4; q++) h2[q] = 0ull;
    float xm1 = 0.f, xm2 = 0.f, xm3 = 0.f;

    for (int tile = 0; tile < SEQ / TT; tile++) {
        const int buf = tile & 1;

        // ---- phase A: half-dots for xh,z; conv; silu ----
        {
            ull wa[8], wz[8];
            #pragma unroll
            for (int qq = 0; qq < 4; qq++) {
                float4 a4 = winp4[4 * p + qq][d];
                wa[2 * qq] = pack2(a4.x, a4.y);
                wa[2 * qq + 1] = pack2(a4.z, a4.w);
                float4 z4 = winp4[4 * p + qq][64 + d];
                wz[2 * qq] = pack2(z4.x, z4.y);
                wz[2 * qq + 1] = pack2(z4.z, z4.w);
            }
            #pragma unroll
            for (int tt = 0; tt < TT; tt++) {
                ull ax = 0ull, az = 0ull;
                const float4* xp4 = (const float4*)&xin_s[buf][j][tt][16 * p];
                #pragma unroll
                for (int qq = 0; qq < 4; qq++) {
                    float4 xv4 = xp4[qq];
                    ull lo = pack2(xv4.x, xv4.y);
                    ull hi = pack2(xv4.z, xv4.w);
                    FMA2(ax, wa[2 * qq], lo, ax);
                    FMA2(az, wz[2 * qq], lo, az);
                    FMA2(ax, wa[2 * qq + 1], hi, ax);
                    FMA2(az, wz[2 * qq + 1], hi, az);
                }
                float2 fx = unpack2(ax), fz = unpack2(az);
                float xh = fx.x + fx.y;
                float z = fz.x + fz.y;
                xh += __shfl_xor_sync(0xffffffffu, xh, 1);
                z  += __shfl_xor_sync(0xffffffffu, z, 1);
                float xc = cb;
                xc = fmaf(cw.x, xm3, xc);
                xc = fmaf(cw.y, xm2, xc);
                xc = fmaf(cw.z, xm1, xc);
                xc = fmaf(cw.w, xh, xc);
                xm3 = xm2; xm2 = xm1; xm1 = xh;
                if (p == 0) {
                    xt_s[j][tt][d] = __fdividef(xc, 1.f + __expf(-xc));
                    sz_s[j][tt][d] = __fdividef(z, 1.f + __expf(-z));
                }
            }
        }
        asm volatile("bar.sync %0, 128;" :: "r"(j + 1) : "memory");

        // ---- phase B: x_proj quarter-dots + dt partials; input prefetch ----
        {
            ull wB[8];
            #pragma unroll
            for (int qq = 0; qq < 4; qq++) {
                float4 b4 = xpw4[qq][u];
                wB[2 * qq] = pack2(b4.x, b4.y);
                wB[2 * qq + 1] = pack2(b4.z, b4.w);
            }
            const float wdv = wdt_s[p][d];
            const uint32_t qoff = (uint32_t)(32 * ((u >> 1) & 1) + 16 * (u & 1)) * 4u;
            const int pos = u >> 2;

            #pragma unroll
            for (int tt = 0; tt < TT; tt++) {
                const uint32_t rowa = xt_a + (uint32_t)tt * 256u;
                ull acc = 0ull;
                #pragma unroll
                for (int qq = 0; qq < 4; qq++) {
                    float4 xv4 = lds128(rowa + qoff + (uint32_t)qq * 16u);
                    FMA2(acc, wB[2 * qq], pack2(xv4.x, xv4.y), acc);
                    FMA2(acc, wB[2 * qq + 1], pack2(xv4.z, xv4.w), acc);
                }
                float2 a2 = unpack2(acc);
                float partial = a2.x + a2.y;
                partial += __shfl_xor_sync(0xffffffffu, partial, 1);
                partial += __shfl_xor_sync(0xffffffffu, partial, 2);
                if ((u & 3) == 0) dbc_s[j][tt][pos] = partial;

                // dt partial: own channel, row p
                float xtv = xt_s[j][tt][d];
                float dv = wdv * xtv;
                dv += __shfl_xor_sync(0xffffffffu, dv, 2);
                dv += __shfl_xor_sync(0xffffffffu, dv, 4);
                dv += __shfl_xor_sync(0xffffffffu, dv, 8);
                dv += __shfl_xor_sync(0xffffffffu, dv, 16);
                if ((lane >> 1) == 0) dtp_s[j][tt][p][w4] = dv;
            }
            if (tid < 128 && tile + 1 < SEQ / TT) {
                int s = tid >> 6, rem = tid & 63;
                float4 v4 = *(const float4*)(g_xr + (size_t)(bb0 + s) * (SEQ * DM)
                                             + (tile + 1) * (TT * DM) + rem * 4);
                *(float4*)&xin_s[buf ^ 1][s][rem >> 3][(rem & 7) * 4] = v4;
            }
        }
        asm volatile("bar.sync %0, 128;" :: "r"(j + 1) : "memory");

        // ---- phase C: delta, scan (8 states/thread), merge, gate, head ----
        #pragma unroll
        for (int tt = 0; tt < TT; tt++) {
            float4 dtp0 = lds128(dtp_a + (uint32_t)tt * 32u);
            float4 dtp1 = lds128(dtp_a + (uint32_t)tt * 32u + 16u);
            const float u0 = (dtp0.x + dtp0.y) + (dtp0.z + dtp0.w);
            const float u1 = (dtp1.x + dtp1.y) + (dtp1.z + dtp1.w);
            const float dpre = fmaf(dtw.x, u0, fmaf(dtw.y, u1, dtb));
            const float delta = dpre > 15.f ? dpre : __logf(1.f + __expf(dpre));
            const float xt = xt_s[j][tt][d];
            const float du = delta * xt;
            const ull du2 = pack2(du, du);
            const uint32_t dba = db_a + (uint32_t)tt * 160u + (uint32_t)(8 * p) * 4u;
            float4 b40 = lds128(dba), b41 = lds128(dba + 16u);
            float4 c40 = lds128(dba + 64u), c41 = lds128(dba + 80u);
            ull y2a = 0ull, y2b = 0ull;

            if (!slow) {
                const float r = __expf(-delta);
                const float rr = r * r;
                float s1 = r, s2 = rr;
                if (p) {                      // start at r^9, r^10
                    float r4 = rr * rr;
                    float r8 = r4 * r4;
                    s1 = r8 * r; s2 = r8 * rr;
                }
                ull cur = pack2(s1, s2);
                const ull rrd = pack2(rr, rr);
                #pragma unroll
                for (int qq = 0; qq < 2; qq++) {
                    float4 b4 = qq ? b41 : b40;
                    float4 c4 = qq ? c41 : c40;
                    ull bp = pack2(b4.x, b4.y), cp = pack2(c4.x, c4.y);
                    ull tmp;
                    MUL2(tmp, bp, du2);
                    FMA2(h2[2 * qq], cur, h2[2 * qq], tmp);
                    FMA2(y2a, h2[2 * qq], cp, y2a);
                    MUL2(cur, cur, rrd);
                    bp = pack2(b4.z, b4.w); cp = pack2(c4.z, c4.w);
                    MUL2(tmp, bp, du2);
                    FMA2(h2[2 * qq + 1], cur, h2[2 * qq + 1], tmp);
                    FMA2(y2b, h2[2 * qq + 1], cp, y2b);
                    if (qq < 1) MUL2(cur, cur, rrd);
                }
            } else {
                #pragma unroll
                for (int qq = 0; qq < 2; qq++) {
                    float4 b4 = qq ? b41 : b40;
                    float4 c4 = qq ? c41 : c40;
                    float4 ap = *(const float4*)&a_s[d][8 * p + 4 * qq];
                    ull dA = pack2(__expf(delta * ap.x), __expf(delta * ap.y));
                    ull bp = pack2(b4.x, b4.y), cp = pack2(c4.x, c4.y);
                    ull tmp;
                    MUL2(tmp, bp, du2);
                    FMA2(h2[2 * qq], dA, h2[2 * qq], tmp);
                    FMA2(y2a, h2[2 * qq], cp, y2a);
                    dA = pack2(__expf(delta * ap.z), __expf(delta * ap.w));
                    bp = pack2(b4.z, b4.w); cp = pack2(c4.z, c4.w);
                    MUL2(tmp, bp, du2);
                    FMA2(h2[2 * qq + 1], dA, h2[2 * qq + 1], tmp);
                    FMA2(y2b, h2[2 * qq + 1], cp, y2b);
                }
            }
            float2 ya = unpack2(y2a), yb = unpack2(y2b);
            float yh = (ya.x + ya.y) + (yb.x + yb.y);
            if (p == 0) yh = fmaf(xt, dpv, yh);           // D-skip once
            yh += __shfl_xor_sync(0xffffffffu, yh, 1);     // merge halves
            float y = yh * sz_s[j][tt][d];
            float acc = y * vv;
            acc += __shfl_xor_sync(0xffffffffu, acc, 2);
            acc += __shfl_xor_sync(0xffffffffu, acc, 4);
            acc += __shfl_xor_sync(0xffffffffu, acc, 8);
            acc += __shfl_xor_sync(0xffffffffu, acc, 16);
            if (lane == 0) part_s[j][tile * TT + tt][w4] = acc;
        }
        // C reads only self/own-warp-written xt/sz/dbc slots of THIS tile;
        // next tile's overwrites are fenced by its phase-A/B barriers.
        asm volatile("bar.sync %0, 128;" :: "r"(j + 1) : "memory");
    }

    __syncthreads();
    if (tid < 128) {
        const int sj = tid & 1;
        const int t = tid >> 1;
        const float4 pv = *(const float4*)&part_s[sj][t][0];
        const float val = (pv.x + pv.y) + (pv.z + pv.w) + c_s;
        const int obb = bb0 + sj;
        out[(obb >> 10) * (SEQ * HW) + t * HW + (obb & (HW - 1))] = val;
    }
}

extern "C" void kernel_launch(void* const* d_in, const int* in_sizes, int n_in,
                              void* d_out, int out_size) {
    const float* x         = (const float*)d_in[0];
    const float* in_proj_w = (const float*)d_in[1];
    const float* conv_w    = (const float*)d_in[2];
    const float* conv_b    = (const float*)d_in[3];
    const float* x_proj_w  = (const float*)d_in[4];
    const float* dt_proj_w = (const float*)d_in[5];
    const float* dt_proj_b = (const float*)d_in[6];
    const float* A_log     = (const float*)d_in[7];
    const float* Dp        = (const float*)d_in[8];
    const float* out_proj_w= (const float*)d_in[9];
    const float* lin1_w    = (const float*)d_in[10];
    const float* lin1_b    = (const float*)d_in[11];
    const float* lin2_w    = (const float*)d_in[12];
    const float* lin2_b    = (const float*)d_in[13];
    float* out = (float*)d_out;

    transpose_kernel<<<2048, 256>>>(x);
    mamba_main<<<1024, 256>>>(in_proj_w, conv_w, conv_b, x_proj_w,
                              dt_proj_w, dt_proj_b, A_log, Dp, out_proj_w,
                              lin1_w, lin1_b, lin2_w, lin2_b, out);
}

// round 15
// speedup vs baseline: 1.0523x; 1.0523x over previous
#include <cuda_runtime.h>
#include <cstdint>

typedef unsigned long long ull;

#define SEQ 64
#define DM 32
#define DI 64
#define HW 1024
#define TT 32

#define FMA2(d, a, b, c) \
    asm("fma.rn.f32x2 %0, %1, %2, %3;" : "=l"(d) : "l"(a), "l"(b), "l"(c))
#define MUL2(d, a, b) \
    asm("mul.rn.f32x2 %0, %1, %2;" : "=l"(d) : "l"(a), "l"(b))
__device__ __forceinline__ ull pack2(float lo, float hi) {
    ull r; asm("mov.b64 %0, {%1, %2};" : "=l"(r) : "f"(lo), "f"(hi)); return r;
}
__device__ __forceinline__ float2 unpack2(ull v) {
    float2 f; asm("mov.b64 {%0, %1}, %2;" : "=f"(f.x), "=f"(f.y) : "l"(v)); return f;
}
__device__ __forceinline__ ull lds64v(uint32_t a) {
    ull v; asm volatile("ld.shared.b64 %0, [%1];" : "=l"(v) : "r"(a)); return v;
}
__device__ __forceinline__ float4 lds128v(uint32_t a) {
    float4 v;
    asm volatile("ld.shared.v4.f32 {%0,%1,%2,%3}, [%4];"
                 : "=f"(v.x), "=f"(v.y), "=f"(v.z), "=f"(v.w) : "r"(a));
    return v;
}

__device__ float g_xr[2 * HW * SEQ * DM];

__global__ __launch_bounds__(256) void transpose_kernel(const float* __restrict__ x) {
    __shared__ float tile[DM][65];
    const int bi = blockIdx.x;
    const int c  = bi & 15;
    const int t  = (bi >> 4) & 63;
    const int b  = bi >> 10;
    const float* src = x + ((b * SEQ + t) * DM) * HW + c * 64;
    const int tid = threadIdx.x;
    #pragma unroll
    for (int i = 0; i < 8; i++) {
        int idx = tid + i * 256;
        tile[idx >> 6][idx & 63] = src[(idx >> 6) * HW + (idx & 63)];
    }
    __syncthreads();
    #pragma unroll
    for (int i = 0; i < 8; i++) {
        int idx = tid + i * 256;
        int hw = idx >> 5, m = idx & 31;
        g_xr[(b * HW + c * 64 + hw) * (SEQ * DM) + t * DM + m] = tile[m][hw];
    }
}

// 256 threads = 4 teams x 64; one sequence per team; TT=32 step tiles (2 tiles).
__global__ __launch_bounds__(256, 2) void mamba_main(
    const float* __restrict__ in_proj_w, const float* __restrict__ conv_w,
    const float* __restrict__ conv_b, const float* __restrict__ x_proj_w,
    const float* __restrict__ dt_proj_w, const float* __restrict__ dt_proj_b,
    const float* __restrict__ A_log, const float* __restrict__ Dp,
    const float* __restrict__ out_proj_w, const float* __restrict__ lin1_w,
    const float* __restrict__ lin1_b, const float* __restrict__ lin2_w,
    const float* __restrict__ lin2_b, float* __restrict__ out)
{
    __shared__ float4 winp4[8][128];       // in_proj 4-wide; r<64 xh, r>=64 z
    __shared__ float4 xpw4[8][64];         // B/C half-row 4-wide, i = 32w + l
    __shared__ ull    wdt_u[64];           // dt rows 0/1 pairs
    __shared__ float  xin_s[2][4][TT][DM]; // double-buffered input tiles (32KB)
    __shared__ float  xt_s[4][TT][64];     // INTERLEAVED (32KB)
    __shared__ float  sz_s[4][TT][DI];     // silu(z) (32KB)
    __shared__ float  dbc_s[4][TT][40];    // [0:16)B,[16:32)C,[32]u0,[33]u1 (20KB)
    __shared__ float  part_s[4][SEQ][2];
    __shared__ float  wm_s[DM];
    __shared__ float  v_s[DI];
    __shared__ float  a_s[DI][18];
    __shared__ float  c_s;
    __shared__ int    slow_s;

    const int tid = threadIdx.x;
    const int team = tid >> 6;
    const int d = tid & 63;
    const int w = (tid >> 5) & 1;
    const int l = tid & 31;

    if (tid == 0) slow_s = 0;
    for (int idx = tid; idx < 1024; idx += 256) {
        int qq = idx >> 7, r = idx & 127;
        winp4[qq][r] = *(const float4*)&in_proj_w[r * DM + 4 * qq];
    }
    for (int idx = tid; idx < 512; idx += 256) {
        int qq = idx >> 6, i = idx & 63;
        int wi = i >> 5, li = i & 31;
        int row = 2 + 16 * wi + (li >> 1), half = li & 1;
        xpw4[qq][i] = *(const float4*)&x_proj_w[row * DI + 32 * half + 4 * qq];
    }
    if (tid < 64) {
        int wi = tid >> 5, li = tid & 31;
        float2 p = *(const float2*)&x_proj_w[wi * DI + 2 * li];
        wdt_u[tid] = pack2(p.x, p.y);
    }
    if (tid < DM) {
        float acc = 0.f;
        #pragma unroll
        for (int k = 0; k < 16; k++) acc = fmaf(lin2_w[k], lin1_w[k * 32 + tid], acc);
        wm_s[tid] = acc;
    }
    if (tid == 0) {
        float c = lin2_b[0];
        #pragma unroll
        for (int k = 0; k < 16; k++) c = fmaf(lin2_w[k], lin1_b[k], c);
        c_s = c;
    }
    __syncthreads();
    if (tid < DI) {
        float acc = 0.f;
        #pragma unroll
        for (int m = 0; m < 32; m++) acc = fmaf(wm_s[m], out_proj_w[m * 64 + tid], acc);
        v_s[tid] = acc;
        int bad = 0;
        #pragma unroll
        for (int n = 0; n < 16; n++) {
            float a = -__expf(A_log[tid * 16 + n]);
            a_s[tid][n] = a;
            if (fabsf(a + (float)(n + 1)) > 1e-4f * (float)(n + 1)) bad = 1;
        }
        if (bad) atomicOr(&slow_s, 1);
    }

    const float4 cw = *(const float4*)(conv_w + d * 4);
    const float cb = conv_b[d];
    const float2 dtw = *(const float2*)(dt_proj_w + d * 2);
    const float dtb = dt_proj_b[d];
    const float dpv = Dp[d];

    const int bb = blockIdx.x * 4 + team;
    const float* xbase = g_xr + (size_t)bb * (SEQ * DM);
    // preload tile 0: 32 steps x 32 floats = 256 float4; 4 per thread
    #pragma unroll
    for (int r = 0; r < 4; r++) {
        int f = d + 64 * r;
        float4 v4 = *(const float4*)(xbase + f * 4);
        *(float4*)&xin_s[0][team][f >> 3][(f & 7) * 4] = v4;
    }
    __syncthreads();
    const float vv = v_s[d];
    const int slow = slow_s;

    const uint32_t winp_a = (uint32_t)__cvta_generic_to_shared(&winp4[0][0]);
    const uint32_t xpw_a  = (uint32_t)__cvta_generic_to_shared(&xpw4[0][0]);
    const uint32_t wdt_a  = (uint32_t)__cvta_generic_to_shared(&wdt_u[0]);
    const uint32_t xt_a   = (uint32_t)__cvta_generic_to_shared(&xt_s[team][0][0]);

    // interleaved slot for own channel
    const int xpos = ((d & 31) >> 2) * 8 + ((d & 32) ? 4 : 0) + (d & 3);
    ull h2[8];
    #pragma unroll
    for (int q = 0; q < 8; q++) h2[q] = 0ull;
    float xm1 = 0.f, xm2 = 0.f, xm3 = 0.f;

    for (int tile = 0; tile < SEQ / TT; tile++) {
        const int buf = tile & 1;

        // ---- phase A: in_proj (both banks) + conv + silu -> xt_s, sz_s ----
        {
            ull wa[16], wz[16];
            #pragma unroll
            for (int qq = 0; qq < 8; qq++) {
                float4 a4 = lds128v(winp_a + (uint32_t)(qq * 128 + d) * 16u);
                wa[2 * qq] = pack2(a4.x, a4.y);
                wa[2 * qq + 1] = pack2(a4.z, a4.w);
                float4 z4 = lds128v(winp_a + (uint32_t)(qq * 128 + 64 + d) * 16u);
                wz[2 * qq] = pack2(z4.x, z4.y);
                wz[2 * qq + 1] = pack2(z4.z, z4.w);
            }
            #pragma unroll 4
            for (int tt = 0; tt < TT; tt++) {
                ull ax = 0ull, az = 0ull;
                const float4* xp4 = (const float4*)xin_s[buf][team][tt];
                #pragma unroll
                for (int qq = 0; qq < 8; qq++) {
                    float4 xv4 = xp4[qq];
                    ull lo = pack2(xv4.x, xv4.y);
                    ull hi = pack2(xv4.z, xv4.w);
                    FMA2(ax, wa[2 * qq], lo, ax);
                    FMA2(az, wz[2 * qq], lo, az);
                    FMA2(ax, wa[2 * qq + 1], hi, ax);
                    FMA2(az, wz[2 * qq + 1], hi, az);
                }
                float2 fx = unpack2(ax), fz = unpack2(az);
                const float xh = fx.x + fx.y;
                const float z = fz.x + fz.y;
                float xc = cb;
                xc = fmaf(cw.x, xm3, xc);
                xc = fmaf(cw.y, xm2, xc);
                xc = fmaf(cw.z, xm1, xc);
                xc = fmaf(cw.w, xh, xc);
                xm3 = xm2; xm2 = xm1; xm1 = xh;
                xt_s[team][tt][xpos] = __fdividef(xc, 1.f + __expf(-xc));
                sz_s[team][tt][d] = __fdividef(z, 1.f + __expf(-z));
            }
        }
        asm volatile("bar.sync %0, 64;" :: "r"(team + 1) : "memory");

        // ---- phase B: x_proj half-rows + dt; input prefetch ----
        {
            const bool ld = (tile + 1 < SEQ / TT);
            float4 pf[4];
            if (ld) {
                #pragma unroll
                for (int r = 0; r < 4; r++) {
                    int f = d + 64 * r;
                    pf[r] = *(const float4*)(xbase + (tile + 1) * (TT * DM) + f * 4);
                }
            }
            ull wB[16];
            const int i = 32 * w + l;
            #pragma unroll
            for (int qq = 0; qq < 8; qq++) {
                float4 b4 = lds128v(xpw_a + (uint32_t)(qq * 64 + i) * 16u);
                wB[2 * qq] = pack2(b4.x, b4.y);
                wB[2 * qq + 1] = pack2(b4.z, b4.w);
            }
            const float2 wdv = unpack2(lds64v(wdt_a + (uint32_t)i * 8u));
            const uint32_t hoff = (uint32_t)(l & 1) * 16u;
            const int d0 = 2 * l;
            const int dtf = (d0 < 32) ? ((d0 >> 2) * 8 + (d0 & 3))
                                      : (((d0 - 32) >> 2) * 8 + 4 + (d0 & 3));
            const int pos = 16 * w + (l >> 1);

            #pragma unroll 4
            for (int tt = 0; tt < TT; tt++) {
                const uint32_t rowa = xt_a + (uint32_t)tt * 256u;
                ull acc = 0ull;
                #pragma unroll
                for (int qq = 0; qq < 8; qq++) {
                    float4 xv4 = lds128v(rowa + (uint32_t)qq * 32u + hoff);
                    FMA2(acc, wB[2 * qq], pack2(xv4.x, xv4.y), acc);
                    FMA2(acc, wB[2 * qq + 1], pack2(xv4.z, xv4.w), acc);
                }
                float2 a2 = unpack2(acc);
                float partial = a2.x + a2.y;
                partial += __shfl_xor_sync(0xffffffffu, partial, 1);
                if (!(l & 1)) dbc_s[team][tt][pos] = partial;

                float2 xv = unpack2(lds64v(rowa + (uint32_t)dtf * 4u));
                float u = fmaf(wdv.y, xv.y, wdv.x * xv.x);
                #pragma unroll
                for (int off = 16; off; off >>= 1)
                    u += __shfl_xor_sync(0xffffffffu, u, off);
                if (l == 0) dbc_s[team][tt][32 + w] = u;
            }
            if (ld) {
                #pragma unroll
                for (int r = 0; r < 4; r++) {
                    int f = d + 64 * r;
                    *(float4*)&xin_s[buf ^ 1][team][f >> 3][(f & 7) * 4] = pf[r];
                }
            }
        }
        asm volatile("bar.sync %0, 64;" :: "r"(team + 1) : "memory");

        // ---- phase C: delta, scan, gate, folded head ----
        #pragma unroll 4
        for (int tt = 0; tt < TT; tt++) {
            const float* db = dbc_s[team][tt];
            const float2 uu = *(const float2*)&db[32];
            const float dpre = fmaf(dtw.x, uu.x, fmaf(dtw.y, uu.y, dtb));
            const float delta = dpre > 15.f ? dpre : __logf(1.f + __expf(dpre));
            const float xt = xt_s[team][tt][xpos];
            const float du = delta * xt;
            const ull du2 = pack2(du, du);
            ull y2a = 0ull, y2b = 0ull;
            if (!slow) {
                const float r = __expf(-delta);
                const float rr = r * r;
                ull cur = pack2(r, rr);
                const ull rrd = pack2(rr, rr);
                #pragma unroll
                for (int qq = 0; qq < 4; qq++) {
                    float4 b4 = *(const float4*)&db[4 * qq];
                    float4 c4 = *(const float4*)&db[16 + 4 * qq];
                    ull bp = pack2(b4.x, b4.y), cp = pack2(c4.x, c4.y);
                    ull tmp;
                    MUL2(tmp, bp, du2);
                    FMA2(h2[2 * qq], cur, h2[2 * qq], tmp);
                    FMA2(y2a, h2[2 * qq], cp, y2a);
                    MUL2(cur, cur, rrd);
                    bp = pack2(b4.z, b4.w); cp = pack2(c4.z, c4.w);
                    MUL2(tmp, bp, du2);
                    FMA2(h2[2 * qq + 1], cur, h2[2 * qq + 1], tmp);
                    FMA2(y2b, h2[2 * qq + 1], cp, y2b);
                    if (qq < 3) MUL2(cur, cur, rrd);
                }
            } else {
                #pragma unroll
                for (int qq = 0; qq < 4; qq++) {
                    float4 b4 = *(const float4*)&db[4 * qq];
                    float4 c4 = *(const float4*)&db[16 + 4 * qq];
                    float4 ap = *(const float4*)&a_s[d][4 * qq];
                    ull dA = pack2(__expf(delta * ap.x), __expf(delta * ap.y));
                    ull bp = pack2(b4.x, b4.y), cp = pack2(c4.x, c4.y);
                    ull tmp;
                    MUL2(tmp, bp, du2);
                    FMA2(h2[2 * qq], dA, h2[2 * qq], tmp);
                    FMA2(y2a, h2[2 * qq], cp, y2a);
                    dA = pack2(__expf(delta * ap.z), __expf(delta * ap.w));
                    bp = pack2(b4.z, b4.w); cp = pack2(c4.z, c4.w);
                    MUL2(tmp, bp, du2);
                    FMA2(h2[2 * qq + 1], dA, h2[2 * qq + 1], tmp);
                    FMA2(y2b, h2[2 * qq + 1], cp, y2b);
                }
            }
            float2 ya = unpack2(y2a), yb = unpack2(y2b);
            float y = (ya.x + ya.y) + (yb.x + yb.y);
            y = fmaf(xt, dpv, y);
            y *= sz_s[team][tt][d];

            float acc = y * vv;
            #pragma unroll
            for (int off = 16; off; off >>= 1)
                acc += __shfl_xor_sync(0xffffffffu, acc, off);
            if (l == 0) part_s[team][tile * TT + tt][w] = acc;
        }
        // C reads only self-written xt/sz slots; dbc reuse fenced by next tile's bar1.
    }

    __syncthreads();
    {
        const int tt = tid >> 2;
        const int jj = tid & 3;
        const float val = part_s[jj][tt][0] + part_s[jj][tt][1] + c_s;
        const int obb = blockIdx.x * 4 + jj;
        out[(obb >> 10) * (SEQ * HW) + tt * HW + (obb & (HW - 1))] = val;
    }
}

extern "C" void kernel_launch(void* const* d_in, const int* in_sizes, int n_in,
                              void* d_out, int out_size) {
    const float* x         = (const float*)d_in[0];
    const float* in_proj_w = (const float*)d_in[1];
    const float* conv_w    = (const float*)d_in[2];
    const float* conv_b    = (const float*)d_in[3];
    const float* x_proj_w  = (const float*)d_in[4];
    const float* dt_proj_w = (const float*)d_in[5];
    const float* dt_proj_b = (const float*)d_in[6];
    const float* A_log     = (const float*)d_in[7];
    const float* Dp        = (const float*)d_in[8];
    const float* out_proj_w= (const float*)d_in[9];
    const float* lin1_w    = (const float*)d_in[10];
    const float* lin1_b    = (const float*)d_in[11];
    const float* lin2_w    = (const float*)d_in[12];
    const float* lin2_b    = (const float*)d_in[13];
    float* out = (float*)d_out;

    transpose_kernel<<<2048, 256>>>(x);
    mamba_main<<<512, 256>>>(in_proj_w, conv_w, conv_b, x_proj_w,
                             dt_proj_w, dt_proj_b, A_log, Dp, out_proj_w,
                             lin1_w, lin1_b, lin2_w, lin2_b, out);
}

// round 16
// speedup vs baseline: 1.5733x; 1.4951x over previous
#include <cuda_runtime.h>
#include <cstdint>

typedef unsigned long long ull;

#define SEQ 64
#define DM 32
#define DI 64
#define HW 1024
#define TT 16

#define FMA2(d, a, b, c) \
    asm("fma.rn.f32x2 %0, %1, %2, %3;" : "=l"(d) : "l"(a), "l"(b), "l"(c))
#define MUL2(d, a, b) \
    asm("mul.rn.f32x2 %0, %1, %2;" : "=l"(d) : "l"(a), "l"(b))
__device__ __forceinline__ ull pack2(float lo, float hi) {
    ull r; asm("mov.b64 %0, {%1, %2};" : "=l"(r) : "f"(lo), "f"(hi)); return r;
}
__device__ __forceinline__ float2 unpack2(ull v) {
    float2 f; asm("mov.b64 {%0, %1}, %2;" : "=f"(f.x), "=f"(f.y) : "l"(v)); return f;
}
__device__ __forceinline__ ull lds64v(uint32_t a) {
    ull v; asm volatile("ld.shared.b64 %0, [%1];" : "=l"(v) : "r"(a)); return v;
}
__device__ __forceinline__ float4 lds128v(uint32_t a) {
    float4 v;
    asm volatile("ld.shared.v4.f32 {%0,%1,%2,%3}, [%4];"
                 : "=f"(v.x), "=f"(v.y), "=f"(v.z), "=f"(v.w) : "r"(a));
    return v;
}

__device__ float g_xr[2 * HW * SEQ * DM];

__global__ __launch_bounds__(256) void transpose_kernel(const float* __restrict__ x) {
    __shared__ float tile[DM][65];
    const int bi = blockIdx.x;
    const int c  = bi & 15;
    const int t  = (bi >> 4) & 63;
    const int b  = bi >> 10;
    const float* src = x + ((b * SEQ + t) * DM) * HW + c * 64;
    const int tid = threadIdx.x;
    #pragma unroll
    for (int i = 0; i < 8; i++) {
        int idx = tid + i * 256;
        tile[idx >> 6][idx & 63] = src[(idx >> 6) * HW + (idx & 63)];
    }
    __syncthreads();
    #pragma unroll
    for (int i = 0; i < 8; i++) {
        int idx = tid + i * 256;
        int hw = idx >> 5, m = idx & 31;
        g_xr[(b * HW + c * 64 + hw) * (SEQ * DM) + t * DM + m] = tile[m][hw];
    }
}

// 256 threads = 4 teams x 64; one sequence per team; TT=16 step tiles.
__global__ __launch_bounds__(256, 2) void mamba_main(
    const float* __restrict__ in_proj_w, const float* __restrict__ conv_w,
    const float* __restrict__ conv_b, const float* __restrict__ x_proj_w,
    const float* __restrict__ dt_proj_w, const float* __restrict__ dt_proj_b,
    const float* __restrict__ A_log, const float* __restrict__ Dp,
    const float* __restrict__ out_proj_w, const float* __restrict__ lin1_w,
    const float* __restrict__ lin1_b, const float* __restrict__ lin2_w,
    const float* __restrict__ lin2_b, float* __restrict__ out)
{
    __shared__ float4 winp4[8][128];       // in_proj 4-wide; r<64 xh, r>=64 z
    __shared__ float4 xpw4[8][64];         // B/C half-row 4-wide, i = 32w + l
    __shared__ ull    wdt_u[64];           // dt rows 0/1 pairs
    __shared__ float  xin_s[2][4][TT][DM]; // double-buffered input tiles
    __shared__ float  xt_s[4][TT][64];     // INTERLEAVED: [h0c0|h1c0|h0c1|h1c1|...]
    __shared__ float  sz_s[4][TT][DI];     // silu(z)
    __shared__ float  dbc_s[4][TT][40];    // [0:16)B,[16:32)C,[32]u0,[33]u1
    __shared__ float  part_s[4][SEQ][2];
    __shared__ float  wm_s[DM];
    __shared__ float  v_s[DI];
    __shared__ float  a_s[DI][18];
    __shared__ float  c_s;
    __shared__ int    slow_s;

    const int tid = threadIdx.x;
    const int team = tid >> 6;
    const int d = tid & 63;
    const int w = (tid >> 5) & 1;
    const int l = tid & 31;

    if (tid == 0) slow_s = 0;
    for (int idx = tid; idx < 1024; idx += 256) {
        int qq = idx >> 7, r = idx & 127;
        winp4[qq][r] = *(const float4*)&in_proj_w[r * DM + 4 * qq];
    }
    for (int idx = tid; idx < 512; idx += 256) {
        int qq = idx >> 6, i = idx & 63;
        int wi = i >> 5, li = i & 31;
        int row = 2 + 16 * wi + (li >> 1), half = li & 1;
        xpw4[qq][i] = *(const float4*)&x_proj_w[row * DI + 32 * half + 4 * qq];
    }
    if (tid < 64) {
        int wi = tid >> 5, li = tid & 31;
        float2 p = *(const float2*)&x_proj_w[wi * DI + 2 * li];
        wdt_u[tid] = pack2(p.x, p.y);
    }
    if (tid < DM) {
        float acc = 0.f;
        #pragma unroll
        for (int k = 0; k < 16; k++) acc = fmaf(lin2_w[k], lin1_w[k * 32 + tid], acc);
        wm_s[tid] = acc;
    }
    if (tid == 0) {
        float c = lin2_b[0];
        #pragma unroll
        for (int k = 0; k < 16; k++) c = fmaf(lin2_w[k], lin1_b[k], c);
        c_s = c;
    }
    __syncthreads();
    if (tid < DI) {
        float acc = 0.f;
        #pragma unroll
        for (int m = 0; m < 32; m++) acc = fmaf(wm_s[m], out_proj_w[m * 64 + tid], acc);
        v_s[tid] = acc;
        int bad = 0;
        #pragma unroll
        for (int n = 0; n < 16; n++) {
            float a = -__expf(A_log[tid * 16 + n]);
            a_s[tid][n] = a;
            if (fabsf(a + (float)(n + 1)) > 1e-4f * (float)(n + 1)) bad = 1;
        }
        if (bad) atomicOr(&slow_s, 1);
    }

    const float4 cw = *(const float4*)(conv_w + d * 4);
    const float cb = conv_b[d];
    const float2 dtw = *(const float2*)(dt_proj_w + d * 2);
    const float dtb = dt_proj_b[d];
    const float dpv = Dp[d];

    const int bb = blockIdx.x * 4 + team;
    const float* xbase = g_xr + (size_t)bb * (SEQ * DM);
    #pragma unroll
    for (int r = 0; r < 2; r++) {
        int f = d + 64 * r;
        float4 v4 = *(const float4*)(xbase + f * 4);
        *(float4*)&xin_s[0][team][f >> 3][(f & 7) * 4] = v4;
    }
    __syncthreads();
    const float vv = v_s[d];
    const int slow = slow_s;

    const uint32_t winp_a = (uint32_t)__cvta_generic_to_shared(&winp4[0][0]);
    const uint32_t xpw_a  = (uint32_t)__cvta_generic_to_shared(&xpw4[0][0]);
    const uint32_t wdt_a  = (uint32_t)__cvta_generic_to_shared(&wdt_u[0]);
    const uint32_t xt_a   = (uint32_t)__cvta_generic_to_shared(&xt_s[team][0][0]);

    const int xpos = ((d & 31) >> 2) * 8 + ((d & 32) ? 4 : 0) + (d & 3);
    ull h2[8];
    #pragma unroll
    for (int q = 0; q < 8; q++) h2[q] = 0ull;
    float xm1 = 0.f, xm2 = 0.f, xm3 = 0.f;

    for (int tile = 0; tile < SEQ / TT; tile++) {
        const int buf = tile & 1;

        // ---- phase A: in_proj (both banks) + conv + silu -> xt_s, sz_s ----
        {
            ull wa[16], wz[16];
            #pragma unroll
            for (int qq = 0; qq < 8; qq++) {
                float4 a4 = lds128v(winp_a + (uint32_t)(qq * 128 + d) * 16u);
                wa[2 * qq] = pack2(a4.x, a4.y);
                wa[2 * qq + 1] = pack2(a4.z, a4.w);
                float4 z4 = lds128v(winp_a + (uint32_t)(qq * 128 + 64 + d) * 16u);
                wz[2 * qq] = pack2(z4.x, z4.y);
                wz[2 * qq + 1] = pack2(z4.z, z4.w);
            }
            #pragma unroll 4
            for (int tt = 0; tt < TT; tt++) {
                ull ax = 0ull, az = 0ull;
                const float4* xp4 = (const float4*)xin_s[buf][team][tt];
                #pragma unroll
                for (int qq = 0; qq < 8; qq++) {
                    float4 xv4 = xp4[qq];
                    ull lo = pack2(xv4.x, xv4.y);
                    ull hi = pack2(xv4.z, xv4.w);
                    FMA2(ax, wa[2 * qq], lo, ax);
                    FMA2(az, wz[2 * qq], lo, az);
                    FMA2(ax, wa[2 * qq + 1], hi, ax);
                    FMA2(az, wz[2 * qq + 1], hi, az);
                }
                float2 fx = unpack2(ax), fz = unpack2(az);
                const float xh = fx.x + fx.y;
                const float z = fz.x + fz.y;
                float xc = cb;
                xc = fmaf(cw.x, xm3, xc);
                xc = fmaf(cw.y, xm2, xc);
                xc = fmaf(cw.z, xm1, xc);
                xc = fmaf(cw.w, xh, xc);
                xm3 = xm2; xm2 = xm1; xm1 = xh;
                xt_s[team][tt][xpos] = __fdividef(xc, 1.f + __expf(-xc));
                sz_s[team][tt][d] = __fdividef(z, 1.f + __expf(-z));
            }
        }
        asm volatile("bar.sync %0, 64;" :: "r"(team + 1) : "memory");

        // ---- phase B: x_proj half-rows + dt; input prefetch ----
        {
            const bool ld = (tile + 1 < SEQ / TT);
            float4 pf[2];
            if (ld) {
                #pragma unroll
                for (int r = 0; r < 2; r++) {
                    int f = d + 64 * r;
                    pf[r] = *(const float4*)(xbase + (tile + 1) * (TT * DM) + f * 4);
                }
            }
            ull wB[16];
            const int i = 32 * w + l;
            #pragma unroll
            for (int qq = 0; qq < 8; qq++) {
                float4 b4 = lds128v(xpw_a + (uint32_t)(qq * 64 + i) * 16u);
                wB[2 * qq] = pack2(b4.x, b4.y);
                wB[2 * qq + 1] = pack2(b4.z, b4.w);
            }
            const float2 wdv = unpack2(lds64v(wdt_a + (uint32_t)i * 8u));
            const uint32_t hoff = (uint32_t)(l & 1) * 16u;
            const int d0 = 2 * l;
            const int dtf = (d0 < 32) ? ((d0 >> 2) * 8 + (d0 & 3))
                                      : (((d0 - 32) >> 2) * 8 + 4 + (d0 & 3));
            const int pos = 16 * w + (l >> 1);

            #pragma unroll 4
            for (int tt = 0; tt < TT; tt++) {
                const uint32_t rowa = xt_a + (uint32_t)tt * 256u;
                ull acc = 0ull;
                #pragma unroll
                for (int qq = 0; qq < 8; qq++) {
                    float4 xv4 = lds128v(rowa + (uint32_t)qq * 32u + hoff);
                    FMA2(acc, wB[2 * qq], pack2(xv4.x, xv4.y), acc);
                    FMA2(acc, wB[2 * qq + 1], pack2(xv4.z, xv4.w), acc);
                }
                float2 a2 = unpack2(acc);
                float partial = a2.x + a2.y;
                partial += __shfl_xor_sync(0xffffffffu, partial, 1);
                if (!(l & 1)) dbc_s[team][tt][pos] = partial;

                float2 xv = unpack2(lds64v(rowa + (uint32_t)dtf * 4u));
                float u = fmaf(wdv.y, xv.y, wdv.x * xv.x);
                #pragma unroll
                for (int off = 16; off; off >>= 1)
                    u += __shfl_xor_sync(0xffffffffu, u, off);
                if (l == 0) dbc_s[team][tt][32 + w] = u;
            }
            if (ld) {
                #pragma unroll
                for (int r = 0; r < 2; r++) {
                    int f = d + 64 * r;
                    *(float4*)&xin_s[buf ^ 1][team][f >> 3][(f & 7) * 4] = pf[r];
                }
            }
        }
        asm volatile("bar.sync %0, 64;" :: "r"(team + 1) : "memory");

        // ---- phase C: C1 (per-step scalars, 8-step halves) + C2 (tight scan) ----
        if (!slow) {
            #pragma unroll
            for (int half = 0; half < 2; half++) {
                float du8[8], r8[8];
                #pragma unroll
                for (int k = 0; k < 8; k++) {
                    const int tt = 8 * half + k;
                    const float2 uu = *(const float2*)&dbc_s[team][tt][32];
                    const float dpre = fmaf(dtw.x, uu.x, fmaf(dtw.y, uu.y, dtb));
                    const float delta = dpre > 15.f ? dpre : __logf(1.f + __expf(dpre));
                    du8[k] = delta * xt_s[team][tt][xpos];
                    r8[k] = __expf(-delta);
                }
                #pragma unroll
                for (int k = 0; k < 8; k++) {
                    const int tt = 8 * half + k;
                    const float* db = dbc_s[team][tt];
                    const float du = du8[k];
                    const ull du2 = pack2(du, du);
                    ull y2a = 0ull, y2b = 0ull;
                    const float r = r8[k];
                    const float rr = r * r;
                    ull cur = pack2(r, rr);
                    const ull rrd = pack2(rr, rr);
                    #pragma unroll
                    for (int qq = 0; qq < 4; qq++) {
                        float4 b4 = *(const float4*)&db[4 * qq];
                        float4 c4 = *(const float4*)&db[16 + 4 * qq];
                        ull bp = pack2(b4.x, b4.y), cp = pack2(c4.x, c4.y);
                        ull tmp;
                        MUL2(tmp, bp, du2);
                        FMA2(h2[2 * qq], cur, h2[2 * qq], tmp);
                        FMA2(y2a, h2[2 * qq], cp, y2a);
                        MUL2(cur, cur, rrd);
                        bp = pack2(b4.z, b4.w); cp = pack2(c4.z, c4.w);
                        MUL2(tmp, bp, du2);
                        FMA2(h2[2 * qq + 1], cur, h2[2 * qq + 1], tmp);
                        FMA2(y2b, h2[2 * qq + 1], cp, y2b);
                        if (qq < 3) MUL2(cur, cur, rrd);
                    }
                    float2 ya = unpack2(y2a), yb = unpack2(y2b);
                    const float xt = xt_s[team][tt][xpos];
                    float y = (ya.x + ya.y) + (yb.x + yb.y);
                    y = fmaf(xt, dpv, y);
                    y *= sz_s[team][tt][d];

                    float acc = y * vv;
                    #pragma unroll
                    for (int off = 16; off; off >>= 1)
                        acc += __shfl_xor_sync(0xffffffffu, acc, off);
                    if (l == 0) part_s[team][tile * TT + tt][w] = acc;
                }
            }
        } else {
            #pragma unroll 4
            for (int tt = 0; tt < TT; tt++) {
                const float* db = dbc_s[team][tt];
                const float2 uu = *(const float2*)&db[32];
                const float dpre = fmaf(dtw.x, uu.x, fmaf(dtw.y, uu.y, dtb));
                const float delta = dpre > 15.f ? dpre : __logf(1.f + __expf(dpre));
                const float xt = xt_s[team][tt][xpos];
                const float du = delta * xt;
                const ull du2 = pack2(du, du);
                ull y2a = 0ull, y2b = 0ull;
                #pragma unroll
                for (int qq = 0; qq < 4; qq++) {
                    float4 b4 = *(const float4*)&db[4 * qq];
                    float4 c4 = *(const float4*)&db[16 + 4 * qq];
                    float4 ap = *(const float4*)&a_s[d][4 * qq];
                    ull dA = pack2(__expf(delta * ap.x), __expf(delta * ap.y));
                    ull bp = pack2(b4.x, b4.y), cp = pack2(c4.x, c4.y);
                    ull tmp;
                    MUL2(tmp, bp, du2);
                    FMA2(h2[2 * qq], dA, h2[2 * qq], tmp);
                    FMA2(y2a, h2[2 * qq], cp, y2a);
                    dA = pack2(__expf(delta * ap.z), __expf(delta * ap.w));
                    bp = pack2(b4.z, b4.w); cp = pack2(c4.z, c4.w);
                    MUL2(tmp, bp, du2);
                    FMA2(h2[2 * qq + 1], dA, h2[2 * qq + 1], tmp);
                    FMA2(y2b, h2[2 * qq + 1], cp, y2b);
                }
                float2 ya = unpack2(y2a), yb = unpack2(y2b);
                float y = (ya.x + ya.y) + (yb.x + yb.y);
                y = fmaf(xt, dpv, y);
                y *= sz_s[team][tt][d];

                float acc = y * vv;
                #pragma unroll
                for (int off = 16; off; off >>= 1)
                    acc += __shfl_xor_sync(0xffffffffu, acc, off);
                if (l == 0) part_s[team][tile * TT + tt][w] = acc;
            }
        }
        // C reads only self-written xt/sz slots; dbc reuse fenced by next tile's bar1.
    }

    __syncthreads();
    {
        const int tt = tid >> 2;
        const int jj = tid & 3;
        const float val = part_s[jj][tt][0] + part_s[jj][tt][1] + c_s;
        const int obb = blockIdx.x * 4 + jj;
        out[(obb >> 10) * (SEQ * HW) + tt * HW + (obb & (HW - 1))] = val;
    }
}

extern "C" void kernel_launch(void* const* d_in, const int* in_sizes, int n_in,
                              void* d_out, int out_size) {
    const float* x         = (const float*)d_in[0];
    const float* in_proj_w = (const float*)d_in[1];
    const float* conv_w    = (const float*)d_in[2];
    const float* conv_b    = (const float*)d_in[3];
    const float* x_proj_w  = (const float*)d_in[4];
    const float* dt_proj_w = (const float*)d_in[5];
    const float* dt_proj_b = (const float*)d_in[6];
    const float* A_log     = (const float*)d_in[7];
    const float* Dp        = (const float*)d_in[8];
    const float* out_proj_w= (const float*)d_in[9];
    const float* lin1_w    = (const float*)d_in[10];
    const float* lin1_b    = (const float*)d_in[11];
    const float* lin2_w    = (const float*)d_in[12];
    const float* lin2_b    = (const float*)d_in[13];
    float* out = (float*)d_out;

    transpose_kernel<<<2048, 256>>>(x);
    mamba_main<<<512, 256>>>(in_proj_w, conv_w, conv_b, x_proj_w,
                             dt_proj_w, dt_proj_b, A_log, Dp, out_proj_w,
                             lin1_w, lin1_b, lin2_w, lin2_b, out);
}

// round 17
// speedup vs baseline: 1.6246x; 1.0326x over previous
#include <cuda_runtime.h>
#include <cstdint>

typedef unsigned long long ull;

#define SEQ 64
#define DM 32
#define DI 64
#define HW 1024
#define TT 16

#define FMA2(d, a, b, c) \
    asm("fma.rn.f32x2 %0, %1, %2, %3;" : "=l"(d) : "l"(a), "l"(b), "l"(c))
#define MUL2(d, a, b) \
    asm("mul.rn.f32x2 %0, %1, %2;" : "=l"(d) : "l"(a), "l"(b))
__device__ __forceinline__ ull pack2(float lo, float hi) {
    ull r; asm("mov.b64 %0, {%1, %2};" : "=l"(r) : "f"(lo), "f"(hi)); return r;
}
__device__ __forceinline__ float2 unpack2(ull v) {
    float2 f; asm("mov.b64 {%0, %1}, %2;" : "=f"(f.x), "=f"(f.y) : "l"(v)); return f;
}
__device__ __forceinline__ ull lds64v(uint32_t a) {
    ull v; asm volatile("ld.shared.b64 %0, [%1];" : "=l"(v) : "r"(a)); return v;
}
__device__ __forceinline__ float4 lds128v(uint32_t a) {
    float4 v;
    asm volatile("ld.shared.v4.f32 {%0,%1,%2,%3}, [%4];"
                 : "=f"(v.x), "=f"(v.y), "=f"(v.z), "=f"(v.w) : "r"(a));
    return v;
}

__device__ float g_xr[2 * HW * SEQ * DM];

__global__ __launch_bounds__(256) void transpose_kernel(const float* __restrict__ x) {
    __shared__ float tile[DM][65];
    const int bi = blockIdx.x;
    const int c  = bi & 15;
    const int t  = (bi >> 4) & 63;
    const int b  = bi >> 10;
    const float* src = x + ((b * SEQ + t) * DM) * HW + c * 64;
    const int tid = threadIdx.x;
    #pragma unroll
    for (int i = 0; i < 8; i++) {
        int idx = tid + i * 256;
        tile[idx >> 6][idx & 63] = src[(idx >> 6) * HW + (idx & 63)];
    }
    __syncthreads();
    #pragma unroll
    for (int i = 0; i < 8; i++) {
        int idx = tid + i * 256;
        int hw = idx >> 5, m = idx & 31;
        g_xr[(b * HW + c * 64 + hw) * (SEQ * DM) + t * DM + m] = tile[m][hw];
    }
}

// 256 threads = 4 teams x 64; one sequence per team; TT=16 step tiles.
__global__ __launch_bounds__(256, 2) void mamba_main(
    const float* __restrict__ in_proj_w, const float* __restrict__ conv_w,
    const float* __restrict__ conv_b, const float* __restrict__ x_proj_w,
    const float* __restrict__ dt_proj_w, const float* __restrict__ dt_proj_b,
    const float* __restrict__ A_log, const float* __restrict__ Dp,
    const float* __restrict__ out_proj_w, const float* __restrict__ lin1_w,
    const float* __restrict__ lin1_b, const float* __restrict__ lin2_w,
    const float* __restrict__ lin2_b, float* __restrict__ out)
{
    __shared__ float4 winp4[8][128];        // in_proj 4-wide; r<64 xh, r>=64 z
    __shared__ float4 xpw4[8][64];          // B/C half-row 4-wide, i = 32w + l
    __shared__ ull    wdt_u[64];            // dt rows 0/1 pairs
    __shared__ float  xin_s[2][4][TT][DM];  // double-buffered input tiles
    __shared__ float  xt_s[4][TT][64];      // INTERLEAVED
    __shared__ float  sz_s[2][4][TT][68];   // silu(z) then y*v (dbl-buf, 68-pad)
    __shared__ float  dbc_s[4][TT][40];     // [0:16)B,[16:32)C,[32]u0,[33]u1
    __shared__ float  part_s[4][SEQ];       // one sum per (team, t)
    __shared__ float  wm_s[DM];
    __shared__ float  v_s[DI];
    __shared__ float  a_s[DI][18];
    __shared__ float  c_s;
    __shared__ int    slow_s;

    const int tid = threadIdx.x;
    const int team = tid >> 6;
    const int d = tid & 63;
    const int w = (tid >> 5) & 1;
    const int l = tid & 31;

    if (tid == 0) slow_s = 0;
    for (int idx = tid; idx < 1024; idx += 256) {
        int qq = idx >> 7, r = idx & 127;
        winp4[qq][r] = *(const float4*)&in_proj_w[r * DM + 4 * qq];
    }
    for (int idx = tid; idx < 512; idx += 256) {
        int qq = idx >> 6, i = idx & 63;
        int wi = i >> 5, li = i & 31;
        int row = 2 + 16 * wi + (li >> 1), half = li & 1;
        xpw4[qq][i] = *(const float4*)&x_proj_w[row * DI + 32 * half + 4 * qq];
    }
    if (tid < 64) {
        int wi = tid >> 5, li = tid & 31;
        float2 p = *(const float2*)&x_proj_w[wi * DI + 2 * li];
        wdt_u[tid] = pack2(p.x, p.y);
    }
    if (tid < DM) {
        float acc = 0.f;
        #pragma unroll
        for (int k = 0; k < 16; k++) acc = fmaf(lin2_w[k], lin1_w[k * 32 + tid], acc);
        wm_s[tid] = acc;
    }
    if (tid == 0) {
        float c = lin2_b[0];
        #pragma unroll
        for (int k = 0; k < 16; k++) c = fmaf(lin2_w[k], lin1_b[k], c);
        c_s = c;
    }
    __syncthreads();
    if (tid < DI) {
        float acc = 0.f;
        #pragma unroll
        for (int m = 0; m < 32; m++) acc = fmaf(wm_s[m], out_proj_w[m * 64 + tid], acc);
        v_s[tid] = acc;
        int bad = 0;
        #pragma unroll
        for (int n = 0; n < 16; n++) {
            float a = -__expf(A_log[tid * 16 + n]);
            a_s[tid][n] = a;
            if (fabsf(a + (float)(n + 1)) > 1e-4f * (float)(n + 1)) bad = 1;
        }
        if (bad) atomicOr(&slow_s, 1);
    }

    const float4 cw = *(const float4*)(conv_w + d * 4);
    const float cb = conv_b[d];
    const float2 dtw = *(const float2*)(dt_proj_w + d * 2);
    const float dtb = dt_proj_b[d];
    const float dpv = Dp[d];

    const int bb = blockIdx.x * 4 + team;
    const float* xbase = g_xr + (size_t)bb * (SEQ * DM);
    #pragma unroll
    for (int r = 0; r < 2; r++) {
        int f = d + 64 * r;
        float4 v4 = *(const float4*)(xbase + f * 4);
        *(float4*)&xin_s[0][team][f >> 3][(f & 7) * 4] = v4;
    }
    __syncthreads();
    const float vv = v_s[d];
    const int slow = slow_s;

    const uint32_t winp_a = (uint32_t)__cvta_generic_to_shared(&winp4[0][0]);
    const uint32_t xpw_a  = (uint32_t)__cvta_generic_to_shared(&xpw4[0][0]);
    const uint32_t wdt_a  = (uint32_t)__cvta_generic_to_shared(&wdt_u[0]);
    const uint32_t xt_a   = (uint32_t)__cvta_generic_to_shared(&xt_s[team][0][0]);

    const int xpos = ((d & 31) >> 2) * 8 + ((d & 32) ? 4 : 0) + (d & 3);
    ull h2[8];
    #pragma unroll
    for (int q = 0; q < 8; q++) h2[q] = 0ull;
    float xm1 = 0.f, xm2 = 0.f, xm3 = 0.f;

    for (int tile = 0; tile < SEQ / TT; tile++) {
        const int buf = tile & 1;

        // ---- phase A: in_proj (both banks) + conv + silu -> xt_s, sz_s[buf] ----
        {
            ull wa[16], wz[16];
            #pragma unroll
            for (int qq = 0; qq < 8; qq++) {
                float4 a4 = lds128v(winp_a + (uint32_t)(qq * 128 + d) * 16u);
                wa[2 * qq] = pack2(a4.x, a4.y);
                wa[2 * qq + 1] = pack2(a4.z, a4.w);
                float4 z4 = lds128v(winp_a + (uint32_t)(qq * 128 + 64 + d) * 16u);
                wz[2 * qq] = pack2(z4.x, z4.y);
                wz[2 * qq + 1] = pack2(z4.z, z4.w);
            }
            #pragma unroll 4
            for (int tt = 0; tt < TT; tt++) {
                ull ax = 0ull, az = 0ull;
                const float4* xp4 = (const float4*)xin_s[buf][team][tt];
                #pragma unroll
                for (int qq = 0; qq < 8; qq++) {
                    float4 xv4 = xp4[qq];
                    ull lo = pack2(xv4.x, xv4.y);
                    ull hi = pack2(xv4.z, xv4.w);
                    FMA2(ax, wa[2 * qq], lo, ax);
                    FMA2(az, wz[2 * qq], lo, az);
                    FMA2(ax, wa[2 * qq + 1], hi, ax);
                    FMA2(az, wz[2 * qq + 1], hi, az);
                }
                float2 fx = unpack2(ax), fz = unpack2(az);
                const float xh = fx.x + fx.y;
                const float z = fz.x + fz.y;
                float xc = cb;
                xc = fmaf(cw.x, xm3, xc);
                xc = fmaf(cw.y, xm2, xc);
                xc = fmaf(cw.z, xm1, xc);
                xc = fmaf(cw.w, xh, xc);
                xm3 = xm2; xm2 = xm1; xm1 = xh;
                xt_s[team][tt][xpos] = __fdividef(xc, 1.f + __expf(-xc));
                sz_s[buf][team][tt][d] = __fdividef(z, 1.f + __expf(-z));
            }
        }
        asm volatile("bar.sync %0, 64;" :: "r"(team + 1) : "memory");

        // ---- phase B: x_proj half-rows + dt; input prefetch ----
        {
            const bool ld = (tile + 1 < SEQ / TT);
            float4 pf[2];
            if (ld) {
                #pragma unroll
                for (int r = 0; r < 2; r++) {
                    int f = d + 64 * r;
                    pf[r] = *(const float4*)(xbase + (tile + 1) * (TT * DM) + f * 4);
                }
            }
            ull wB[16];
            const int i = 32 * w + l;
            #pragma unroll
            for (int qq = 0; qq < 8; qq++) {
                float4 b4 = lds128v(xpw_a + (uint32_t)(qq * 64 + i) * 16u);
                wB[2 * qq] = pack2(b4.x, b4.y);
                wB[2 * qq + 1] = pack2(b4.z, b4.w);
            }
            const float2 wdv = unpack2(lds64v(wdt_a + (uint32_t)i * 8u));
            const uint32_t hoff = (uint32_t)(l & 1) * 16u;
            const int d0 = 2 * l;
            const int dtf = (d0 < 32) ? ((d0 >> 2) * 8 + (d0 & 3))
                                      : (((d0 - 32) >> 2) * 8 + 4 + (d0 & 3));
            const int pos = 16 * w + (l >> 1);

            #pragma unroll 4
            for (int tt = 0; tt < TT; tt++) {
                const uint32_t rowa = xt_a + (uint32_t)tt * 256u;
                ull acc = 0ull;
                #pragma unroll
                for (int qq = 0; qq < 8; qq++) {
                    float4 xv4 = lds128v(rowa + (uint32_t)qq * 32u + hoff);
                    FMA2(acc, wB[2 * qq], pack2(xv4.x, xv4.y), acc);
                    FMA2(acc, wB[2 * qq + 1], pack2(xv4.z, xv4.w), acc);
                }
                float2 a2 = unpack2(acc);
                float partial = a2.x + a2.y;
                partial += __shfl_xor_sync(0xffffffffu, partial, 1);
                if (!(l & 1)) dbc_s[team][tt][pos] = partial;

                float2 xv = unpack2(lds64v(rowa + (uint32_t)dtf * 4u));
                float u = fmaf(wdv.y, xv.y, wdv.x * xv.x);
                #pragma unroll
                for (int off = 16; off; off >>= 1)
                    u += __shfl_xor_sync(0xffffffffu, u, off);
                if (l == 0) dbc_s[team][tt][32 + w] = u;
            }
            if (ld) {
                #pragma unroll
                for (int r = 0; r < 2; r++) {
                    int f = d + 64 * r;
                    *(float4*)&xin_s[buf ^ 1][team][f >> 3][(f & 7) * 4] = pf[r];
                }
            }
        }
        asm volatile("bar.sync %0, 64;" :: "r"(team + 1) : "memory");

        // ---- phase C: C1 scalars + C2 scan; y*v stored (no per-step reduce) ----
        if (!slow) {
            #pragma unroll
            for (int half = 0; half < 2; half++) {
                float du8[8], r8a[8];
                #pragma unroll
                for (int k = 0; k < 8; k++) {
                    const int tt = 8 * half + k;
                    const float2 uu = *(const float2*)&dbc_s[team][tt][32];
                    const float dpre = fmaf(dtw.x, uu.x, fmaf(dtw.y, uu.y, dtb));
                    const float delta = dpre > 15.f ? dpre : __logf(1.f + __expf(dpre));
                    du8[k] = delta * xt_s[team][tt][xpos];
                    r8a[k] = __expf(-delta);
                }
                #pragma unroll
                for (int k = 0; k < 8; k++) {
                    const int tt = 8 * half + k;
                    const float* db = dbc_s[team][tt];
                    const float du = du8[k];
                    const ull du2 = pack2(du, du);
                    ull y2a = 0ull, y2b = 0ull;
                    const float r = r8a[k];
                    const float r2 = r * r;
                    const float r4 = r2 * r2;
                    const float r8v = r4 * r4;
                    const ull r2d = pack2(r2, r2);
                    const ull r4d = pack2(r4, r4);
                    const ull r8d = pack2(r8v, r8v);
                    ull curq[8];
                    curq[0] = pack2(r, r2);
                    MUL2(curq[1], curq[0], r2d);
                    MUL2(curq[2], curq[0], r4d);
                    MUL2(curq[3], curq[1], r4d);
                    MUL2(curq[4], curq[0], r8d);
                    MUL2(curq[5], curq[1], r8d);
                    MUL2(curq[6], curq[2], r8d);
                    MUL2(curq[7], curq[3], r8d);
                    #pragma unroll
                    for (int qq = 0; qq < 4; qq++) {
                        float4 b4 = *(const float4*)&db[4 * qq];
                        float4 c4 = *(const float4*)&db[16 + 4 * qq];
                        ull bp = pack2(b4.x, b4.y), cp = pack2(c4.x, c4.y);
                        ull tmp;
                        MUL2(tmp, bp, du2);
                        FMA2(h2[2 * qq], curq[2 * qq], h2[2 * qq], tmp);
                        FMA2(y2a, h2[2 * qq], cp, y2a);
                        bp = pack2(b4.z, b4.w); cp = pack2(c4.z, c4.w);
                        MUL2(tmp, bp, du2);
                        FMA2(h2[2 * qq + 1], curq[2 * qq + 1], h2[2 * qq + 1], tmp);
                        FMA2(y2b, h2[2 * qq + 1], cp, y2b);
                    }
                    float2 ya = unpack2(y2a), yb = unpack2(y2b);
                    const float xt = xt_s[team][tt][xpos];
                    float y = (ya.x + ya.y) + (yb.x + yb.y);
                    y = fmaf(xt, dpv, y);
                    y *= sz_s[buf][team][tt][d];
                    sz_s[buf][team][tt][d] = y * vv;
                }
            }
        } else {
            #pragma unroll 4
            for (int tt = 0; tt < TT; tt++) {
                const float* db = dbc_s[team][tt];
                const float2 uu = *(const float2*)&db[32];
                const float dpre = fmaf(dtw.x, uu.x, fmaf(dtw.y, uu.y, dtb));
                const float delta = dpre > 15.f ? dpre : __logf(1.f + __expf(dpre));
                const float xt = xt_s[team][tt][xpos];
                const float du = delta * xt;
                const ull du2 = pack2(du, du);
                ull y2a = 0ull, y2b = 0ull;
                #pragma unroll
                for (int qq = 0; qq < 4; qq++) {
                    float4 b4 = *(const float4*)&db[4 * qq];
                    float4 c4 = *(const float4*)&db[16 + 4 * qq];
                    float4 ap = *(const float4*)&a_s[d][4 * qq];
                    ull dA = pack2(__expf(delta * ap.x), __expf(delta * ap.y));
                    ull bp = pack2(b4.x, b4.y), cp = pack2(c4.x, c4.y);
                    ull tmp;
                    MUL2(tmp, bp, du2);
                    FMA2(h2[2 * qq], dA, h2[2 * qq], tmp);
                    FMA2(y2a, h2[2 * qq], cp, y2a);
                    dA = pack2(__expf(delta * ap.z), __expf(delta * ap.w));
                    bp = pack2(b4.z, b4.w); cp = pack2(c4.z, c4.w);
                    MUL2(tmp, bp, du2);
                    FMA2(h2[2 * qq + 1], dA, h2[2 * qq + 1], tmp);
                    FMA2(y2b, h2[2 * qq + 1], cp, y2b);
                }
                float2 ya = unpack2(y2a), yb = unpack2(y2b);
                float y = (ya.x + ya.y) + (yb.x + yb.y);
                y = fmaf(xt, dpv, y);
                y *= sz_s[buf][team][tt][d];
                sz_s[buf][team][tt][d] = y * vv;
            }
        }
        asm volatile("bar.sync %0, 64;" :: "r"(team + 1) : "memory");

        // ---- per-tile deferred head reduction: 4 threads per t ----
        {
            const int tl = d >> 2;          // t within tile (0..15)
            const int q4 = d & 3;           // channel quarter
            const float* yrow = &sz_s[buf][team][tl][16 * q4];
            float4 a0 = *(const float4*)(yrow);
            float4 a1 = *(const float4*)(yrow + 4);
            float4 a2 = *(const float4*)(yrow + 8);
            float4 a3 = *(const float4*)(yrow + 12);
            float s = ((a0.x + a0.y) + (a0.z + a0.w))
                    + ((a1.x + a1.y) + (a1.z + a1.w))
                    + ((a2.x + a2.y) + (a2.z + a2.w))
                    + ((a3.x + a3.y) + (a3.z + a3.w));
            s += __shfl_xor_sync(0xffffffffu, s, 1);
            s += __shfl_xor_sync(0xffffffffu, s, 2);
            if (q4 == 0) part_s[team][tile * TT + tl] = s;
        }
        // next tile's A writes sz_s[buf^1] (other parity) and xt_s own slots:
        // no race with this reduction; dbc reuse fenced by next tile's bar1.
    }

    __syncthreads();
    {
        const int tt = tid >> 2;
        const int jj = tid & 3;
        const float val = part_s[jj][tt] + c_s;
        const int obb = blockIdx.x * 4 + jj;
        out[(obb >> 10) * (SEQ * HW) + tt * HW + (obb & (HW - 1))] = val;
    }
}

extern "C" void kernel_launch(void* const* d_in, const int* in_sizes, int n_in,
                              void* d_out, int out_size) {
    const float* x         = (const float*)d_in[0];
    const float* in_proj_w = (const float*)d_in[1];
    const float* conv_w    = (const float*)d_in[2];
    const float* conv_b    = (const float*)d_in[3];
    const float* x_proj_w  = (const float*)d_in[4];
    const float* dt_proj_w = (const float*)d_in[5];
    const float* dt_proj_b = (const float*)d_in[6];
    const float* A_log     = (const float*)d_in[7];
    const float* Dp        = (const float*)d_in[8];
    const float* out_proj_w= (const float*)d_in[9];
    const float* lin1_w    = (const float*)d_in[10];
    const float* lin1_b    = (const float*)d_in[11];
    const float* lin2_w    = (const float*)d_in[12];
    const float* lin2_b    = (const float*)d_in[13];
    float* out = (float*)d_out;

    transpose_kernel<<<2048, 256>>>(x);
    mamba_main<<<512, 256>>>(in_proj_w, conv_w, conv_b, x_proj_w,
                             dt_proj_w, dt_proj_b, A_log, Dp, out_proj_w,
                             lin1_w, lin1_b, lin2_w, lin2_b, out);
}